// round 15
// baseline (speedup 1.0000x reference)
#include <cuda_runtime.h>
#include <cuda_fp16.h>
#include <math.h>
#include <stdint.h>

#define N_TOK 4096
#define DIMV 1024
#define HIDV 4096
#define NE 128
#define TOPKV 4
#define RNK 128
#define CAPV 256
#define M_ASSIGN (N_TOK*TOPKV)
#define LDU 20            // smem row stride in uints (40 halves = 80 bytes): conflict-free
#define BUFB (128*LDU*4)  // bytes per 128-row smem buffer (10240)
#define ABUFB (32*LDU*4)  // bytes per 32-row smem buffer (2560)

// ---------------- device scratch (static, zero-init at module load) ----------------
__device__ float  g_logits[N_TOK*NE];               // 2 MB
__device__ __half g_xeff[N_TOK*DIMV];               // 8 MB
__device__ __half g_h[NE*CAPV*RNK];                 // 8 MB
__device__ __half g_ya[(size_t)M_ASSIGN*HIDV];      // 128 MB, assignment-major LoRA outputs
__device__ int    g_topi[M_ASSIGN];
__device__ float  g_scores[M_ASSIGN];
__device__ int    g_pos[M_ASSIGN];
__device__ int    g_slot_tok[NE*CAPV];
__device__ int    g_slot_m[NE*CAPV];
__device__ float  g_slot_s[NE*CAPV];
__device__ int    g_cnt[NE];
__device__ unsigned g_hist[256];
__device__ unsigned g_rank;
__device__ unsigned g_prefix;
__device__ float  g_thr;

__device__ __forceinline__ unsigned pkh2(float lo, float hi) {
    __half2 h = __floats2half2_rn(lo, hi);
    return *reinterpret_cast<unsigned*>(&h);
}

__device__ __forceinline__ void mma_f16(float* d, const unsigned* a, const unsigned* b) {
    asm volatile(
        "mma.sync.aligned.m16n8k16.row.col.f32.f16.f16.f32 "
        "{%0,%1,%2,%3}, {%4,%5,%6,%7}, {%8,%9}, {%0,%1,%2,%3};"
        : "+f"(d[0]), "+f"(d[1]), "+f"(d[2]), "+f"(d[3])
        : "r"(a[0]), "r"(a[1]), "r"(a[2]), "r"(a[3]), "r"(b[0]), "r"(b[1]));
}

__device__ __forceinline__ void ldsm4(unsigned& r0, unsigned& r1, unsigned& r2, unsigned& r3,
                                      uint32_t addr) {
    asm volatile("ldmatrix.sync.aligned.m8n8.x4.shared.b16 {%0,%1,%2,%3}, [%4];"
                 : "=r"(r0), "=r"(r1), "=r"(r2), "=r"(r3) : "r"(addr));
}

// ---------------- init ----------------
__global__ void init_kernel() {
    int t = threadIdx.x;
    if (t == 0) { g_rank = 419430u; g_prefix = 0u; }
    if (t < 256) g_hist[t] = 0u;
}

// ---------------- router: fp32 SIMT 64x64 tiles (exact decisions) ----------------
__global__ void __launch_bounds__(256) router_kernel(
    const float* __restrict__ A, const float* __restrict__ B,
    const float* __restrict__ bias, float* __restrict__ C)
{
    const int K = DIMV, N = NE;
    __shared__ float As[16][68];
    __shared__ float Bs[16][68];
    int bm = blockIdx.y * 64, bn = blockIdx.x * 64;
    int tid = threadIdx.x;
    int lr = tid >> 2;
    int lc = (tid & 3) * 4;
    int tx = tid & 15, ty = tid >> 4;
    const float* Ap = A + (size_t)(bm + lr) * K + lc;
    const float* Bp = B + (size_t)(bn + lr) * K + lc;
    float acc[4][4] = {};
    for (int k0 = 0; k0 < K; k0 += 16) {
        float4 a4 = *(const float4*)(Ap + k0);
        float4 b4 = *(const float4*)(Bp + k0);
        __syncthreads();
        As[lc + 0][lr] = a4.x; As[lc + 1][lr] = a4.y; As[lc + 2][lr] = a4.z; As[lc + 3][lr] = a4.w;
        Bs[lc + 0][lr] = b4.x; Bs[lc + 1][lr] = b4.y; Bs[lc + 2][lr] = b4.z; Bs[lc + 3][lr] = b4.w;
        __syncthreads();
#pragma unroll
        for (int kk = 0; kk < 16; kk++) {
            float4 av = *(const float4*)&As[kk][ty * 4];
            float4 bv = *(const float4*)&Bs[kk][tx * 4];
            float a[4] = { av.x, av.y, av.z, av.w };
            float b[4] = { bv.x, bv.y, bv.z, bv.w };
#pragma unroll
            for (int i = 0; i < 4; i++)
#pragma unroll
                for (int j = 0; j < 4; j++)
                    acc[i][j] += a[i] * b[j];
        }
    }
    float4 bb = *(const float4*)&bias[bn + tx * 4];
    float b[4] = { bb.x, bb.y, bb.z, bb.w };
#pragma unroll
    for (int i = 0; i < 4; i++) {
        float* cp = C + (size_t)(bm + ty * 4 + i) * N + bn + tx * 4;
        *(float4*)cp = make_float4(acc[i][0] + b[0], acc[i][1] + b[1], acc[i][2] + b[2], acc[i][3] + b[3]);
    }
}

// ---------------- radix select: exact order statistic a[419430] of |logits| ----------------
__global__ void hist_kernel(int shift) {
    __shared__ unsigned h[256];
    int tid = threadIdx.x;
    h[tid] = 0u;
    __syncthreads();
    unsigned prefix = g_prefix;
#pragma unroll
    for (int j = 0; j < 4; j++) {
        int idx = (blockIdx.x * 4 + j) * 256 + tid;
        unsigned u = __float_as_uint(fabsf(g_logits[idx]));
        bool ok = (shift == 24) || ((u >> (shift + 8)) == prefix);
        if (ok) atomicAdd(&h[(u >> shift) & 255], 1u);
    }
    __syncthreads();
    atomicAdd(&g_hist[tid], h[tid]);
}

__global__ void __launch_bounds__(256) pick_kernel(int shift) {
    int tid = threadIdx.x;
    int lane = tid & 31, warp = tid >> 5;
    unsigned c = g_hist[tid];
    unsigned v = c;
#pragma unroll
    for (int off = 1; off < 32; off <<= 1) {
        unsigned o = __shfl_up_sync(0xffffffffu, v, off);
        if (lane >= off) v += o;
    }
    __shared__ unsigned ws[8];
    if (lane == 31) ws[warp] = v;
    __syncthreads();
    unsigned woff = 0;
#pragma unroll
    for (int w = 0; w < 8; w++)
        if (w < warp) woff += ws[w];
    unsigned inc = v + woff;
    unsigned exc = inc - c;
    unsigned r = g_rank;
    if (r < inc && r >= exc) {
        g_rank = r - exc;
        unsigned p = (g_prefix << 8) | (unsigned)tid;
        g_prefix = p;
        if (shift == 0) g_thr = __uint_as_float(p);
    }
    g_hist[tid] = 0u;
}

// ---------------- fused top-4 + softmax + xeff (one warp per token; fp16 xeff out) ---------
__global__ void __launch_bounds__(128) topk_xeff_kernel(const float* __restrict__ x,
                                                        const float* __restrict__ diag) {
    int warp = threadIdx.x >> 5;
    int lane = threadIdx.x & 31;
    int n = blockIdx.x * 4 + warp;
    float thr = g_thr;
    const float* row = g_logits + (size_t)n * NE;
    float v[4]; int idx[4];
#pragma unroll
    for (int j = 0; j < 4; j++) {
        int e = lane + j * 32;
        float xv = row[e];
        if (fabsf(xv) < thr) xv = 0.0f;
        v[j] = xv; idx[j] = e;
    }
    float tv[4]; int ti[4];
#pragma unroll
    for (int sel = 0; sel < 4; sel++) {
        float bv = v[0]; int bi = idx[0];
#pragma unroll
        for (int j = 1; j < 4; j++)
            if (v[j] > bv || (v[j] == bv && idx[j] < bi)) { bv = v[j]; bi = idx[j]; }
#pragma unroll
        for (int off = 16; off; off >>= 1) {
            float ov = __shfl_xor_sync(0xffffffffu, bv, off);
            int   oi = __shfl_xor_sync(0xffffffffu, bi, off);
            if (ov > bv || (ov == bv && oi < bi)) { bv = ov; bi = oi; }
        }
        tv[sel] = bv; ti[sel] = bi;   // warp-uniform after reduction
#pragma unroll
        for (int j = 0; j < 4; j++)
            if (idx[j] == bi) v[j] = -INFINITY;
    }
    float m = tv[0];
    float ex[4], sum = 0.0f;
#pragma unroll
    for (int k = 0; k < 4; k++) { ex[k] = expf(tv[k] - m); sum += ex[k]; }
    float s[4];
#pragma unroll
    for (int k = 0; k < 4; k++) s[k] = ex[k] / sum;
    if (lane < 4) {
        g_topi[n * 4 + lane] = ti[lane];
        g_scores[n * 4 + lane] = s[lane];
    }
    const float* d0 = diag + (size_t)ti[0] * DIMV;
    const float* d1 = diag + (size_t)ti[1] * DIMV;
    const float* d2 = diag + (size_t)ti[2] * DIMV;
    const float* d3 = diag + (size_t)ti[3] * DIMV;
    const float* xr = x + (size_t)n * DIMV;
    __half* xe = g_xeff + (size_t)n * DIMV;
#pragma unroll
    for (int it = 0; it < 8; it++) {
        int d = lane * 4 + it * 128;
        float4 a = *(const float4*)&d0[d];
        float4 b = *(const float4*)&d1[d];
        float4 c = *(const float4*)&d2[d];
        float4 e = *(const float4*)&d3[d];
        float4 xv = *(const float4*)&xr[d];
        float ox = xv.x * (s[0]*a.x + s[1]*b.x + s[2]*c.x + s[3]*e.x);
        float oy = xv.y * (s[0]*a.y + s[1]*b.y + s[2]*c.y + s[3]*e.y);
        float oz = xv.z * (s[0]*a.z + s[1]*b.z + s[2]*c.z + s[3]*e.z);
        float ow = xv.w * (s[0]*a.w + s[1]*b.w + s[2]*c.w + s[3]*e.w);
        *(uint2*)&xe[d] = make_uint2(pkh2(ox, oy), pkh2(oz, ow));
    }
}

// ---------------- deterministic capacity positions (ballot scan, matches cumsum order) -----
__global__ void __launch_bounds__(256) pos_kernel() {
    int e = blockIdx.x;
    int tid = threadIdx.x;
    int lane = tid & 31, warp = tid >> 5;
    __shared__ int swc[8];
    int base = 0;
    for (int chunk = 0; chunk < M_ASSIGN / 256; chunk++) {
        int m = chunk * 256 + tid;
        int flag = (g_topi[m] == e) ? 1 : 0;
        unsigned mask = __ballot_sync(0xffffffffu, flag);
        int wcnt = __popc(mask);
        int wpre = __popc(mask & ((1u << lane) - 1u));
        if (lane == 0) swc[warp] = wcnt;
        __syncthreads();
        int woff = 0, tot = 0;
#pragma unroll
        for (int w = 0; w < 8; w++) {
            int cw = swc[w];
            if (w < warp) woff += cw;
            tot += cw;
        }
        if (flag) {
            int pos = base + woff + wpre;
            g_pos[m] = pos;
            if (pos < CAPV) {
                g_slot_tok[e * CAPV + pos] = m >> 2;
                g_slot_m[e * CAPV + pos] = m;
                g_slot_s[e * CAPV + pos] = g_scores[m];
            }
        }
        base += tot;
        __syncthreads();
    }
    if (tid == 0) g_cnt[e] = (base < CAPV) ? base : CAPV;
}

// ---------------- fp16 tensor-core GEMM family (pipelined, double-buffered) ----------------
// MODE 0: diag path + fused LoRA combine (A=g_xeff fp16, B=Wp, bias=bp, C=out)
// MODE 1: LoRA down, rows 0..127 (A=x fp32 gathered, B=W1[e], bias=b1[e], relu -> g_h fp16)
// MODE 2: LoRA up, rows 0..127 (A=g_h[e] fp16, B=W2[e], scale -> g_ya[m] fp16)
template<int MODE, int KDIM>
__global__ void __launch_bounds__(256) mma_gemm_kernel(
    const float* __restrict__ Ain, const float* __restrict__ Bin,
    const float* __restrict__ bias, float* __restrict__ Cout, int Ncols)
{
    constexpr bool A_HALF = (MODE != 1);
    constexpr int T = KDIM / 32;
    __shared__ unsigned As[2][128 * LDU];
    __shared__ unsigned Bs[2][128 * LDU];
    __shared__ int sm_pos[512];

    const int e = (MODE == 0) ? 0 : blockIdx.z;
    int bm, bn;
    const float* A = Ain;
    const __half* Ah = reinterpret_cast<const __half*>(Ain);
    const float* B = Bin;
    const float* bp = bias;
    int cnt = 0;
    if (MODE == 0) {
        bm = blockIdx.y * 128; bn = blockIdx.x * 128;
    } else {
        cnt = g_cnt[e];
        bm = blockIdx.y * 128;
        if (bm >= cnt) return;
        bn = blockIdx.x * 128;
        if (MODE == 1) {
            B = Bin + (size_t)e * RNK * KDIM;
            bp = bias + e * RNK;
        } else {
            Ah = reinterpret_cast<const __half*>(Ain) + (size_t)e * CAPV * RNK;
            B = Bin + (size_t)e * HIDV * RNK;
            bp = bias + (size_t)e * HIDV;
        }
    }

    const int tid = threadIdx.x;
    const float* Arow[4];
    const __half* Ahrow[4];
    const float* Brow[4];
    int soff[4];   // uint index: r*LDU + c/2
#pragma unroll
    for (int i = 0; i < 4; i++) {
        int idx = tid + i * 256;
        int r = idx >> 3;
        int c = (idx & 7) * 4;
        int grow;
        if (MODE == 1) grow = g_slot_tok[e * CAPV + bm + r];
        else grow = bm + r;
        if (A_HALF) Ahrow[i] = Ah + (size_t)grow * KDIM + c;
        else        Arow[i]  = A + (size_t)grow * KDIM + c;
        Brow[i] = B + (size_t)(bn + r) * KDIM + c;
        soff[i] = r * LDU + (c >> 1);
    }

    const int wid = tid >> 5, lane = tid & 31;
    const int wm = (wid & 1) * 64;
    const int wn = (wid >> 1) * 32;
    const int gid = lane >> 2, tg = lane & 3;

    uint32_t aBase = (uint32_t)__cvta_generic_to_shared(&As[0][0])
                   + (uint32_t)(wm + (lane & 7) + ((lane >> 3) & 1) * 8) * 80u
                   + ((lane >> 4) & 1) * 16u;
    uint32_t bBase = (uint32_t)__cvta_generic_to_shared(&Bs[0][0])
                   + (uint32_t)(wn + (lane >> 4) * 8 + (lane & 7)) * 80u
                   + ((lane >> 3) & 1) * 16u;

    float acc[4][4][4] = {};

    // prefetch tile 0
    uint2  ua[4];
    float4 va[4], vb[4];
#pragma unroll
    for (int i = 0; i < 4; i++) {
        if (A_HALF) ua[i] = *(const uint2*)(Ahrow[i]);
        else        va[i] = *(const float4*)(Arow[i]);
        vb[i] = *(const float4*)(Brow[i]);
    }

    for (int t = 0; t < T; t++) {
        const int buf = t & 1;
        unsigned* as = As[buf];
        unsigned* bs = Bs[buf];
#pragma unroll
        for (int i = 0; i < 4; i++) {
            if (A_HALF) {
                as[soff[i]]     = ua[i].x;
                as[soff[i] + 1] = ua[i].y;
            } else {
                as[soff[i]]     = pkh2(va[i].x, va[i].y);
                as[soff[i] + 1] = pkh2(va[i].z, va[i].w);
            }
            bs[soff[i]]     = pkh2(vb[i].x, vb[i].y);
            bs[soff[i] + 1] = pkh2(vb[i].z, vb[i].w);
        }
        if (t + 1 < T) {
            int k0 = (t + 1) * 32;
#pragma unroll
            for (int i = 0; i < 4; i++) {
                if (A_HALF) ua[i] = *(const uint2*)(Ahrow[i] + k0);
                else        va[i] = *(const float4*)(Arow[i] + k0);
                vb[i] = *(const float4*)(Brow[i] + k0);
            }
        }
        __syncthreads();
        uint32_t aB = aBase + (uint32_t)buf * BUFB;
        uint32_t bB = bBase + (uint32_t)buf * BUFB;
#pragma unroll
        for (int ks = 0; ks < 2; ks++) {
            unsigned afr[4][4];
            unsigned bfr[4][2];
#pragma unroll
            for (int mi = 0; mi < 4; mi++)
                ldsm4(afr[mi][0], afr[mi][1], afr[mi][2], afr[mi][3],
                      aB + (uint32_t)mi * 1280u + (uint32_t)ks * 32u);
#pragma unroll
            for (int p = 0; p < 2; p++)
                ldsm4(bfr[2*p][0], bfr[2*p][1], bfr[2*p+1][0], bfr[2*p+1][1],
                      bB + (uint32_t)p * 1280u + (uint32_t)ks * 32u);
#pragma unroll
            for (int mi = 0; mi < 4; mi++)
#pragma unroll
                for (int ni = 0; ni < 4; ni++)
                    mma_f16(acc[mi][ni], afr[mi], bfr[ni]);
        }
    }

    if (MODE == 0) {
        for (int i = tid; i < 512; i += 256)
            sm_pos[i] = g_pos[(bm + (i >> 2)) * 4 + (i & 3)];
        __syncthreads();
    }

#pragma unroll
    for (int mi = 0; mi < 4; mi++) {
        int row0 = wm + mi * 16 + gid;
        int row1 = row0 + 8;
        if (MODE == 0) {
#pragma unroll
            for (int ni = 0; ni < 4; ni++) {
                int colg = bn + wn + ni * 8 + tg * 2;
                float2 bb = *(const float2*)&bp[colg];
                float v0 = acc[mi][ni][0] + bb.x;
                float v1 = acc[mi][ni][1] + bb.y;
                float v2 = acc[mi][ni][2] + bb.x;
                float v3 = acc[mi][ni][3] + bb.y;
#pragma unroll
                for (int k = 0; k < 4; k++) {
                    if (sm_pos[row0 * 4 + k] < CAPV) {
                        unsigned yw = *(const unsigned*)&g_ya[((size_t)((bm + row0) * 4 + k)) * HIDV + colg];
                        float2 yv = __half22float2(*reinterpret_cast<__half2*>(&yw));
                        v0 += yv.x; v1 += yv.y;
                    }
                    if (sm_pos[row1 * 4 + k] < CAPV) {
                        unsigned yw = *(const unsigned*)&g_ya[((size_t)((bm + row1) * 4 + k)) * HIDV + colg];
                        float2 yv = __half22float2(*reinterpret_cast<__half2*>(&yw));
                        v2 += yv.x; v3 += yv.y;
                    }
                }
                *(float2*)&Cout[(size_t)(bm + row0) * Ncols + colg] = make_float2(v0, v1);
                *(float2*)&Cout[(size_t)(bm + row1) * Ncols + colg] = make_float2(v2, v3);
            }
        } else if (MODE == 1) {
#pragma unroll
            for (int ni = 0; ni < 4; ni++) {
                int colg = bn + wn + ni * 8 + tg * 2;
                float2 bb = *(const float2*)&bp[colg];
                int cc0 = bm + row0, cc1 = bm + row1;
                if (cc0 < cnt) {
                    *(unsigned*)&g_h[((size_t)e * CAPV + cc0) * RNK + colg] =
                        pkh2(fmaxf(acc[mi][ni][0] + bb.x, 0.f), fmaxf(acc[mi][ni][1] + bb.y, 0.f));
                }
                if (cc1 < cnt) {
                    *(unsigned*)&g_h[((size_t)e * CAPV + cc1) * RNK + colg] =
                        pkh2(fmaxf(acc[mi][ni][2] + bb.x, 0.f), fmaxf(acc[mi][ni][3] + bb.y, 0.f));
                }
            }
        } else {
            int cc0 = bm + row0, cc1 = bm + row1;
            int m0 = -1, m1 = -1;
            float s0 = 0.f, s1 = 0.f;
            if (cc0 < cnt) { m0 = g_slot_m[e * CAPV + cc0]; s0 = g_slot_s[e * CAPV + cc0]; }
            if (cc1 < cnt) { m1 = g_slot_m[e * CAPV + cc1]; s1 = g_slot_s[e * CAPV + cc1]; }
#pragma unroll
            for (int ni = 0; ni < 4; ni++) {
                int colg = bn + wn + ni * 8 + tg * 2;
                float2 bb = *(const float2*)&bp[colg];
                if (m0 >= 0)
                    *(unsigned*)&g_ya[(size_t)m0 * HIDV + colg] =
                        pkh2(s0 * (acc[mi][ni][0] + bb.x), s0 * (acc[mi][ni][1] + bb.y));
                if (m1 >= 0)
                    *(unsigned*)&g_ya[(size_t)m1 * HIDV + colg] =
                        pkh2(s1 * (acc[mi][ni][2] + bb.x), s1 * (acc[mi][ni][3] + bb.y));
            }
        }
    }
}

// ---------------- LoRA-down OVERFLOW: rows 128..cnt in 32-row tiles (K=1024) --------------
// h = relu(x_gathered @ W1^T + b1) — same chunk/ks order as MODE1 ⇒ bitwise-identical h
__global__ void __launch_bounds__(256) gemm1ov_kernel(
    const float* __restrict__ x, const float* __restrict__ Bin,
    const float* __restrict__ bias)
{
    __shared__ unsigned As[2][32 * LDU];
    __shared__ unsigned Bs[2][128 * LDU];

    const int e = blockIdx.z;
    const int cnt = g_cnt[e];
    const int bm = 128 + blockIdx.y * 32;
    if (bm >= cnt) return;
    const float* B = Bin + (size_t)e * RNK * DIMV;
    const float* bp = bias + e * RNK;

    const int tid = threadIdx.x;
    const int rA = tid >> 3;
    const int cA = (tid & 7) * 4;
    const int tok = g_slot_tok[e * CAPV + bm + rA];
    const float* Arow = x + (size_t)tok * DIMV + cA;
    const int soffA = rA * LDU + (cA >> 1);
    const float* Brow[4];
    int soffB[4];
#pragma unroll
    for (int i = 0; i < 4; i++) {
        int idx = tid + i * 256;
        int r = idx >> 3;
        int c = (idx & 7) * 4;
        Brow[i] = B + (size_t)r * DIMV + c;
        soffB[i] = r * LDU + (c >> 1);
    }

    const int wid = tid >> 5, lane = tid & 31;
    const int wm = (wid & 1) * 16;
    const int wn = (wid >> 1) * 32;
    const int gid = lane >> 2, tg = lane & 3;

    uint32_t aBase = (uint32_t)__cvta_generic_to_shared(&As[0][0])
                   + (uint32_t)(wm + (lane & 7) + ((lane >> 3) & 1) * 8) * 80u
                   + ((lane >> 4) & 1) * 16u;
    uint32_t bBase = (uint32_t)__cvta_generic_to_shared(&Bs[0][0])
                   + (uint32_t)(wn + (lane >> 4) * 8 + (lane & 7)) * 80u
                   + ((lane >> 3) & 1) * 16u;

    float acc[4][4] = {};

    float4 va = *(const float4*)(Arow);
    float4 vb[4];
#pragma unroll
    for (int i = 0; i < 4; i++) vb[i] = *(const float4*)(Brow[i]);

    for (int t = 0; t < DIMV / 32; t++) {
        const int buf = t & 1;
        unsigned* as = As[buf];
        unsigned* bs = Bs[buf];
        as[soffA]     = pkh2(va.x, va.y);
        as[soffA + 1] = pkh2(va.z, va.w);
#pragma unroll
        for (int i = 0; i < 4; i++) {
            bs[soffB[i]]     = pkh2(vb[i].x, vb[i].y);
            bs[soffB[i] + 1] = pkh2(vb[i].z, vb[i].w);
        }
        if (t + 1 < DIMV / 32) {
            int k0 = (t + 1) * 32;
            va = *(const float4*)(Arow + k0);
#pragma unroll
            for (int i = 0; i < 4; i++) vb[i] = *(const float4*)(Brow[i] + k0);
        }
        __syncthreads();
        uint32_t aB = aBase + (uint32_t)buf * ABUFB;
        uint32_t bB = bBase + (uint32_t)buf * BUFB;
#pragma unroll
        for (int ks = 0; ks < 2; ks++) {
            unsigned afr[4];
            unsigned bfr[4][2];
            ldsm4(afr[0], afr[1], afr[2], afr[3], aB + (uint32_t)ks * 32u);
#pragma unroll
            for (int p = 0; p < 2; p++)
                ldsm4(bfr[2*p][0], bfr[2*p][1], bfr[2*p+1][0], bfr[2*p+1][1],
                      bB + (uint32_t)p * 1280u + (uint32_t)ks * 32u);
#pragma unroll
            for (int ni = 0; ni < 4; ni++)
                mma_f16(acc[ni], afr, bfr[ni]);
        }
    }

    int row0 = wm + gid;
    int row1 = row0 + 8;
    int cc0 = bm + row0, cc1 = bm + row1;
#pragma unroll
    for (int ni = 0; ni < 4; ni++) {
        int colg = wn + ni * 8 + tg * 2;
        float2 bb = *(const float2*)&bp[colg];
        if (cc0 < cnt)
            *(unsigned*)&g_h[((size_t)e * CAPV + cc0) * RNK + colg] =
                pkh2(fmaxf(acc[ni][0] + bb.x, 0.f), fmaxf(acc[ni][1] + bb.y, 0.f));
        if (cc1 < cnt)
            *(unsigned*)&g_h[((size_t)e * CAPV + cc1) * RNK + colg] =
                pkh2(fmaxf(acc[ni][2] + bb.x, 0.f), fmaxf(acc[ni][3] + bb.y, 0.f));
    }
}

// ---------------- LoRA-up OVERFLOW: rows 128..cnt in 32-row tiles (early-exit grid) --------
__global__ void __launch_bounds__(256) gemm2ov_kernel(
    const float* __restrict__ Bin, const float* __restrict__ bias)
{
    __shared__ unsigned As[2][32 * LDU];
    __shared__ unsigned Bs[2][128 * LDU];

    const int e = blockIdx.z;
    const int cnt = g_cnt[e];
    const int bm = 128 + blockIdx.y * 32;
    if (bm >= cnt) return;
    const int bn = blockIdx.x * 128;
    const __half* Ah = g_h + (size_t)e * CAPV * RNK;
    const float* B = Bin + (size_t)e * HIDV * RNK;
    const float* bp = bias + (size_t)e * HIDV;

    const int tid = threadIdx.x;
    const int rA = tid >> 3;
    const int cA = (tid & 7) * 4;
    const __half* Ahrow = Ah + (size_t)(bm + rA) * RNK + cA;
    const int soffA = rA * LDU + (cA >> 1);
    const float* Brow[4];
    int soffB[4];
#pragma unroll
    for (int i = 0; i < 4; i++) {
        int idx = tid + i * 256;
        int r = idx >> 3;
        int c = (idx & 7) * 4;
        Brow[i] = B + (size_t)(bn + r) * RNK + c;
        soffB[i] = r * LDU + (c >> 1);
    }

    const int wid = tid >> 5, lane = tid & 31;
    const int wm = (wid & 1) * 16;
    const int wn = (wid >> 1) * 32;
    const int gid = lane >> 2, tg = lane & 3;

    uint32_t aBase = (uint32_t)__cvta_generic_to_shared(&As[0][0])
                   + (uint32_t)(wm + (lane & 7) + ((lane >> 3) & 1) * 8) * 80u
                   + ((lane >> 4) & 1) * 16u;
    uint32_t bBase = (uint32_t)__cvta_generic_to_shared(&Bs[0][0])
                   + (uint32_t)(wn + (lane >> 4) * 8 + (lane & 7)) * 80u
                   + ((lane >> 3) & 1) * 16u;

    float acc[4][4] = {};

    uint2 ua = *(const uint2*)(Ahrow);
    float4 vb[4];
#pragma unroll
    for (int i = 0; i < 4; i++) vb[i] = *(const float4*)(Brow[i]);

    for (int t = 0; t < 4; t++) {
        const int buf = t & 1;
        unsigned* as = As[buf];
        unsigned* bs = Bs[buf];
        as[soffA]     = ua.x;
        as[soffA + 1] = ua.y;
#pragma unroll
        for (int i = 0; i < 4; i++) {
            bs[soffB[i]]     = pkh2(vb[i].x, vb[i].y);
            bs[soffB[i] + 1] = pkh2(vb[i].z, vb[i].w);
        }
        if (t + 1 < 4) {
            int k0 = (t + 1) * 32;
            ua = *(const uint2*)(Ahrow + k0);
#pragma unroll
            for (int i = 0; i < 4; i++) vb[i] = *(const float4*)(Brow[i] + k0);
        }
        __syncthreads();
        uint32_t aB = aBase + (uint32_t)buf * ABUFB;
        uint32_t bB = bBase + (uint32_t)buf * BUFB;
#pragma unroll
        for (int ks = 0; ks < 2; ks++) {
            unsigned afr[4];
            unsigned bfr[4][2];
            ldsm4(afr[0], afr[1], afr[2], afr[3], aB + (uint32_t)ks * 32u);
#pragma unroll
            for (int p = 0; p < 2; p++)
                ldsm4(bfr[2*p][0], bfr[2*p][1], bfr[2*p+1][0], bfr[2*p+1][1],
                      bB + (uint32_t)p * 1280u + (uint32_t)ks * 32u);
#pragma unroll
            for (int ni = 0; ni < 4; ni++)
                mma_f16(acc[ni], afr, bfr[ni]);
        }
    }

    int row0 = wm + gid;
    int row1 = row0 + 8;
    int cc0 = bm + row0, cc1 = bm + row1;
    int m0 = -1, m1 = -1;
    float s0 = 0.f, s1 = 0.f;
    if (cc0 < cnt) { m0 = g_slot_m[e * CAPV + cc0]; s0 = g_slot_s[e * CAPV + cc0]; }
    if (cc1 < cnt) { m1 = g_slot_m[e * CAPV + cc1]; s1 = g_slot_s[e * CAPV + cc1]; }
#pragma unroll
    for (int ni = 0; ni < 4; ni++) {
        int colg = bn + wn + ni * 8 + tg * 2;
        float2 bb = *(const float2*)&bp[colg];
        if (m0 >= 0)
            *(unsigned*)&g_ya[(size_t)m0 * HIDV + colg] =
                pkh2(s0 * (acc[ni][0] + bb.x), s0 * (acc[ni][1] + bb.y));
        if (m1 >= 0)
            *(unsigned*)&g_ya[(size_t)m1 * HIDV + colg] =
                pkh2(s1 * (acc[ni][2] + bb.x), s1 * (acc[ni][3] + bb.y));
    }
}

// ---------------- host ----------------
extern "C" void kernel_launch(void* const* d_in, const int* in_sizes, int n_in,
                              void* d_out, int out_size) {
    const float* x    = (const float*)d_in[0];
    const float* Wr   = (const float*)d_in[1];
    const float* br   = (const float*)d_in[2];
    const float* diag = (const float*)d_in[3];
    const float* Wp   = (const float*)d_in[4];
    const float* bp   = (const float*)d_in[5];
    const float* W1   = (const float*)d_in[6];
    const float* b1   = (const float*)d_in[7];
    const float* W2   = (const float*)d_in[8];
    const float* b2   = (const float*)d_in[9];
    float* out = (float*)d_out;

    float* p_logits = nullptr;
    void* p_xeff = nullptr;
    void* p_h = nullptr;
    cudaGetSymbolAddress((void**)&p_logits, g_logits);
    cudaGetSymbolAddress(&p_xeff, g_xeff);
    cudaGetSymbolAddress(&p_h, g_h);

    init_kernel<<<1, 256>>>();

    // router logits (exact fp32 — discrete decisions depend on these)
    router_kernel<<<dim3(NE / 64, N_TOK / 64), 256>>>(x, Wr, br, p_logits);

    // exact order statistic a[419430] of |logits| — smem-aggregated 8-bit radix
    for (int shift = 24; shift >= 0; shift -= 8) {
        hist_kernel<<<512, 256>>>(shift);
        pick_kernel<<<1, 256>>>(shift);
    }

    topk_xeff_kernel<<<N_TOK / 4, 128>>>(x, diag);
    pos_kernel<<<NE, 256>>>();

    // LoRA down main: rows 0..127 per expert
    mma_gemm_kernel<1, DIMV><<<dim3(1, 1, NE), 256>>>(x, W1, b1, nullptr, RNK);

    // LoRA down overflow: rows 128..cnt in 32-row tiles
    gemm1ov_kernel<<<dim3(1, 4, NE), 256>>>(x, W1, b1);

    // LoRA up main: rows 0..127 per expert
    mma_gemm_kernel<2, RNK><<<dim3(HIDV / 128, 1, NE), 256>>>((const float*)p_h, W2, b2, nullptr, HIDV);

    // LoRA up overflow: rows 128..cnt in 32-row tiles (most blocks exit immediately)
    gemm2ov_kernel<<<dim3(HIDV / 128, 4, NE), 256>>>(W2, b2);

    // diag path + fused combine: out = xeff @ Wp^T + bp + sum_k ya[4n+k]
    mma_gemm_kernel<0, DIMV><<<dim3(HIDV / 128, N_TOK / 128), 256>>>((const float*)p_xeff, Wp, bp, out, HIDV);
}

// round 16
// speedup vs baseline: 1.0264x; 1.0264x over previous
#include <cuda_runtime.h>
#include <cuda_fp16.h>
#include <math.h>
#include <stdint.h>

#define N_TOK 4096
#define DIMV 1024
#define HIDV 4096
#define NE 128
#define TOPKV 4
#define RNK 128
#define CAPV 256
#define M_ASSIGN (N_TOK*TOPKV)
#define LDU 20            // smem row stride in uints (40 halves = 80 bytes): conflict-free
#define BUFB (128*LDU*4)  // bytes per 128-row smem buffer (10240)
#define ABUFB (32*LDU*4)  // bytes per 32-row smem buffer (2560)
#define NCAND 16384       // candidate buffer (expected ~1.8K sharing 16-bit prefix)

// ---------------- device scratch (static, zero-init at module load) ----------------
__device__ float  g_logits[N_TOK*NE];               // 2 MB
__device__ __half g_xeff[N_TOK*DIMV];               // 8 MB
__device__ __half g_h[NE*CAPV*RNK];                 // 8 MB
__device__ __half g_ya[(size_t)M_ASSIGN*HIDV];      // 128 MB, assignment-major LoRA outputs
__device__ int    g_topi[M_ASSIGN];
__device__ float  g_scores[M_ASSIGN];
__device__ int    g_pos[M_ASSIGN];
__device__ int    g_slot_tok[NE*CAPV];
__device__ int    g_slot_m[NE*CAPV];
__device__ float  g_slot_s[NE*CAPV];
__device__ int    g_cnt[NE];
__device__ unsigned g_hist[256];
__device__ unsigned g_cand[NCAND];
__device__ int    g_ncand;
__device__ unsigned g_rank;
__device__ unsigned g_prefix;
__device__ float  g_thr;

__device__ __forceinline__ unsigned pkh2(float lo, float hi) {
    __half2 h = __floats2half2_rn(lo, hi);
    return *reinterpret_cast<unsigned*>(&h);
}

__device__ __forceinline__ void mma_f16(float* d, const unsigned* a, const unsigned* b) {
    asm volatile(
        "mma.sync.aligned.m16n8k16.row.col.f32.f16.f16.f32 "
        "{%0,%1,%2,%3}, {%4,%5,%6,%7}, {%8,%9}, {%0,%1,%2,%3};"
        : "+f"(d[0]), "+f"(d[1]), "+f"(d[2]), "+f"(d[3])
        : "r"(a[0]), "r"(a[1]), "r"(a[2]), "r"(a[3]), "r"(b[0]), "r"(b[1]));
}

__device__ __forceinline__ void ldsm4(unsigned& r0, unsigned& r1, unsigned& r2, unsigned& r3,
                                      uint32_t addr) {
    asm volatile("ldmatrix.sync.aligned.m8n8.x4.shared.b16 {%0,%1,%2,%3}, [%4];"
                 : "=r"(r0), "=r"(r1), "=r"(r2), "=r"(r3) : "r"(addr));
}

// ---------------- init ----------------
__global__ void init_kernel() {
    int t = threadIdx.x;
    if (t == 0) { g_rank = 419430u; g_prefix = 0u; g_ncand = 0; }
    if (t < 256) g_hist[t] = 0u;
}

// ---------------- router: fp32 SIMT 64x64 tiles (exact decisions) ----------------
__global__ void __launch_bounds__(256) router_kernel(
    const float* __restrict__ A, const float* __restrict__ B,
    const float* __restrict__ bias, float* __restrict__ C)
{
    const int K = DIMV, N = NE;
    __shared__ float As[16][68];
    __shared__ float Bs[16][68];
    int bm = blockIdx.y * 64, bn = blockIdx.x * 64;
    int tid = threadIdx.x;
    int lr = tid >> 2;
    int lc = (tid & 3) * 4;
    int tx = tid & 15, ty = tid >> 4;
    const float* Ap = A + (size_t)(bm + lr) * K + lc;
    const float* Bp = B + (size_t)(bn + lr) * K + lc;
    float acc[4][4] = {};
    for (int k0 = 0; k0 < K; k0 += 16) {
        float4 a4 = *(const float4*)(Ap + k0);
        float4 b4 = *(const float4*)(Bp + k0);
        __syncthreads();
        As[lc + 0][lr] = a4.x; As[lc + 1][lr] = a4.y; As[lc + 2][lr] = a4.z; As[lc + 3][lr] = a4.w;
        Bs[lc + 0][lr] = b4.x; Bs[lc + 1][lr] = b4.y; Bs[lc + 2][lr] = b4.z; Bs[lc + 3][lr] = b4.w;
        __syncthreads();
#pragma unroll
        for (int kk = 0; kk < 16; kk++) {
            float4 av = *(const float4*)&As[kk][ty * 4];
            float4 bv = *(const float4*)&Bs[kk][tx * 4];
            float a[4] = { av.x, av.y, av.z, av.w };
            float b[4] = { bv.x, bv.y, bv.z, bv.w };
#pragma unroll
            for (int i = 0; i < 4; i++)
#pragma unroll
                for (int j = 0; j < 4; j++)
                    acc[i][j] += a[i] * b[j];
        }
    }
    float4 bb = *(const float4*)&bias[bn + tx * 4];
    float b[4] = { bb.x, bb.y, bb.z, bb.w };
#pragma unroll
    for (int i = 0; i < 4; i++) {
        float* cp = C + (size_t)(bm + ty * 4 + i) * N + bn + tx * 4;
        *(float4*)cp = make_float4(acc[i][0] + b[0], acc[i][1] + b[1], acc[i][2] + b[2], acc[i][3] + b[3]);
    }
}

// ---------------- exact order statistic a[419430] of |logits| ----------------
// pass 1 hist: top 8 bits (exponent-heavy => hot bins). Per-warp replica histograms.
__global__ void __launch_bounds__(256) hist24_kernel() {
    __shared__ unsigned h[8][256];
    int tid = threadIdx.x;
    int warp = tid >> 5;
    for (int i = tid; i < 2048; i += 256) ((unsigned*)h)[i] = 0u;
    __syncthreads();
#pragma unroll
    for (int j = 0; j < 4; j++) {
        int idx = (blockIdx.x * 4 + j) * 256 + tid;
        unsigned u = __float_as_uint(fabsf(g_logits[idx]));
        atomicAdd(&h[warp][u >> 24], 1u);
    }
    __syncthreads();
    unsigned s = 0;
#pragma unroll
    for (int w = 0; w < 8; w++) s += h[w][tid];
    if (s) atomicAdd(&g_hist[tid], s);
}

// pass 2 hist: bits [16:24) filtered by top-8 prefix (sparse hits)
__global__ void __launch_bounds__(256) hist16_kernel() {
    __shared__ unsigned h[256];
    int tid = threadIdx.x;
    h[tid] = 0u;
    __syncthreads();
    unsigned prefix = g_prefix;
#pragma unroll
    for (int j = 0; j < 4; j++) {
        int idx = (blockIdx.x * 4 + j) * 256 + tid;
        unsigned u = __float_as_uint(fabsf(g_logits[idx]));
        if ((u >> 24) == prefix) atomicAdd(&h[(u >> 16) & 255], 1u);
    }
    __syncthreads();
    if (h[tid]) atomicAdd(&g_hist[tid], h[tid]);
}

// parallel pick over 256 bins (self-zeroing), appends 8 bits to prefix
__global__ void __launch_bounds__(256) pick_kernel() {
    int tid = threadIdx.x;
    int lane = tid & 31, warp = tid >> 5;
    unsigned c = g_hist[tid];
    unsigned v = c;
#pragma unroll
    for (int off = 1; off < 32; off <<= 1) {
        unsigned o = __shfl_up_sync(0xffffffffu, v, off);
        if (lane >= off) v += o;
    }
    __shared__ unsigned ws[8];
    if (lane == 31) ws[warp] = v;
    __syncthreads();
    unsigned woff = 0;
#pragma unroll
    for (int w = 0; w < 8; w++)
        if (w < warp) woff += ws[w];
    unsigned inc = v + woff;
    unsigned exc = inc - c;
    unsigned r = g_rank;
    if (r < inc && r >= exc) {
        g_rank = r - exc;
        g_prefix = (g_prefix << 8) | (unsigned)tid;
    }
    g_hist[tid] = 0u;
}

// collect all |logit| bit patterns sharing the selected 16-bit prefix (~1.8K expected)
__global__ void __launch_bounds__(256) collect_kernel() {
    int tid = threadIdx.x;
    unsigned prefix = g_prefix;
#pragma unroll
    for (int j = 0; j < 4; j++) {
        int idx = (blockIdx.x * 4 + j) * 256 + tid;
        unsigned u = __float_as_uint(fabsf(g_logits[idx]));
        if ((u >> 16) == prefix) {
            int p = atomicAdd(&g_ncand, 1);
            if (p < NCAND) g_cand[p] = u;
        }
    }
}

// resolve low 16 bits among candidates via two 8-bit histogram levels (one block)
__global__ void __launch_bounds__(256) final_pick_kernel() {
    __shared__ unsigned h[256];
    __shared__ unsigned ws[8];
    __shared__ unsigned sel_s, rank_s;
    int tid = threadIdx.x;
    int lane = tid & 31, warp = tid >> 5;
    int n = g_ncand;
    if (n > NCAND) n = NCAND;
    unsigned rank = g_rank;
    unsigned pfx = g_prefix;   // 16 bits
    // level A: bits [8:16)
    h[tid] = 0u;
    __syncthreads();
    for (int i = tid; i < n; i += 256) atomicAdd(&h[(g_cand[i] >> 8) & 255], 1u);
    __syncthreads();
    {
        unsigned c = h[tid];
        unsigned v = c;
#pragma unroll
        for (int off = 1; off < 32; off <<= 1) {
            unsigned o = __shfl_up_sync(0xffffffffu, v, off);
            if (lane >= off) v += o;
        }
        if (lane == 31) ws[warp] = v;
        __syncthreads();
        unsigned woff = 0;
#pragma unroll
        for (int w = 0; w < 8; w++)
            if (w < warp) woff += ws[w];
        unsigned inc = v + woff;
        unsigned exc = inc - c;
        if (rank < inc && rank >= exc) { sel_s = (unsigned)tid; rank_s = rank - exc; }
    }
    __syncthreads();
    unsigned sel = sel_s;
    unsigned r2 = rank_s;
    // level B: bits [0:8) filtered
    h[tid] = 0u;
    __syncthreads();
    for (int i = tid; i < n; i += 256) {
        unsigned u = g_cand[i];
        if (((u >> 8) & 255) == sel) atomicAdd(&h[u & 255], 1u);
    }
    __syncthreads();
    {
        unsigned c = h[tid];
        unsigned v = c;
#pragma unroll
        for (int off = 1; off < 32; off <<= 1) {
            unsigned o = __shfl_up_sync(0xffffffffu, v, off);
            if (lane >= off) v += o;
        }
        if (lane == 31) ws[warp] = v;
        __syncthreads();
        unsigned woff = 0;
#pragma unroll
        for (int w = 0; w < 8; w++)
            if (w < warp) woff += ws[w];
        unsigned inc = v + woff;
        unsigned exc = inc - c;
        if (r2 < inc && r2 >= exc)
            g_thr = __uint_as_float((pfx << 16) | (sel << 8) | (unsigned)tid);
    }
}

// ---------------- fused top-4 + softmax + xeff (one warp per token; fp16 xeff out) ---------
__global__ void __launch_bounds__(128) topk_xeff_kernel(const float* __restrict__ x,
                                                        const float* __restrict__ diag) {
    int warp = threadIdx.x >> 5;
    int lane = threadIdx.x & 31;
    int n = blockIdx.x * 4 + warp;
    float thr = g_thr;
    const float* row = g_logits + (size_t)n * NE;
    float v[4]; int idx[4];
#pragma unroll
    for (int j = 0; j < 4; j++) {
        int e = lane + j * 32;
        float xv = row[e];
        if (fabsf(xv) < thr) xv = 0.0f;
        v[j] = xv; idx[j] = e;
    }
    float tv[4]; int ti[4];
#pragma unroll
    for (int sel = 0; sel < 4; sel++) {
        float bv = v[0]; int bi = idx[0];
#pragma unroll
        for (int j = 1; j < 4; j++)
            if (v[j] > bv || (v[j] == bv && idx[j] < bi)) { bv = v[j]; bi = idx[j]; }
#pragma unroll
        for (int off = 16; off; off >>= 1) {
            float ov = __shfl_xor_sync(0xffffffffu, bv, off);
            int   oi = __shfl_xor_sync(0xffffffffu, bi, off);
            if (ov > bv || (ov == bv && oi < bi)) { bv = ov; bi = oi; }
        }
        tv[sel] = bv; ti[sel] = bi;   // warp-uniform after reduction
#pragma unroll
        for (int j = 0; j < 4; j++)
            if (idx[j] == bi) v[j] = -INFINITY;
    }
    float m = tv[0];
    float ex[4], sum = 0.0f;
#pragma unroll
    for (int k = 0; k < 4; k++) { ex[k] = expf(tv[k] - m); sum += ex[k]; }
    float s[4];
#pragma unroll
    for (int k = 0; k < 4; k++) s[k] = ex[k] / sum;
    if (lane < 4) {
        g_topi[n * 4 + lane] = ti[lane];
        g_scores[n * 4 + lane] = s[lane];
    }
    const float* d0 = diag + (size_t)ti[0] * DIMV;
    const float* d1 = diag + (size_t)ti[1] * DIMV;
    const float* d2 = diag + (size_t)ti[2] * DIMV;
    const float* d3 = diag + (size_t)ti[3] * DIMV;
    const float* xr = x + (size_t)n * DIMV;
    __half* xe = g_xeff + (size_t)n * DIMV;
#pragma unroll
    for (int it = 0; it < 8; it++) {
        int d = lane * 4 + it * 128;
        float4 a = *(const float4*)&d0[d];
        float4 b = *(const float4*)&d1[d];
        float4 c = *(const float4*)&d2[d];
        float4 e = *(const float4*)&d3[d];
        float4 xv = *(const float4*)&xr[d];
        float ox = xv.x * (s[0]*a.x + s[1]*b.x + s[2]*c.x + s[3]*e.x);
        float oy = xv.y * (s[0]*a.y + s[1]*b.y + s[2]*c.y + s[3]*e.y);
        float oz = xv.z * (s[0]*a.z + s[1]*b.z + s[2]*c.z + s[3]*e.z);
        float ow = xv.w * (s[0]*a.w + s[1]*b.w + s[2]*c.w + s[3]*e.w);
        *(uint2*)&xe[d] = make_uint2(pkh2(ox, oy), pkh2(oz, ow));
    }
}

// ---------------- deterministic capacity positions (ballot scan, matches cumsum order) -----
__global__ void __launch_bounds__(256) pos_kernel() {
    int e = blockIdx.x;
    int tid = threadIdx.x;
    int lane = tid & 31, warp = tid >> 5;
    __shared__ int swc[8];
    int base = 0;
    for (int chunk = 0; chunk < M_ASSIGN / 256; chunk++) {
        int m = chunk * 256 + tid;
        int flag = (g_topi[m] == e) ? 1 : 0;
        unsigned mask = __ballot_sync(0xffffffffu, flag);
        int wcnt = __popc(mask);
        int wpre = __popc(mask & ((1u << lane) - 1u));
        if (lane == 0) swc[warp] = wcnt;
        __syncthreads();
        int woff = 0, tot = 0;
#pragma unroll
        for (int w = 0; w < 8; w++) {
            int cw = swc[w];
            if (w < warp) woff += cw;
            tot += cw;
        }
        if (flag) {
            int pos = base + woff + wpre;
            g_pos[m] = pos;
            if (pos < CAPV) {
                g_slot_tok[e * CAPV + pos] = m >> 2;
                g_slot_m[e * CAPV + pos] = m;
                g_slot_s[e * CAPV + pos] = g_scores[m];
            }
        }
        base += tot;
        __syncthreads();
    }
    if (tid == 0) g_cnt[e] = (base < CAPV) ? base : CAPV;
}

// ---------------- fp16 tensor-core GEMM family (pipelined, double-buffered) ----------------
// MODE 0: diag path + fused LoRA combine (A=g_xeff fp16, B=Wp, bias=bp, C=out)
// MODE 1: LoRA down (A=x fp32 gathered, B=W1[e], bias=b1[e], relu -> g_h fp16)
// MODE 2: LoRA up, rows 0..127 (A=g_h[e] fp16, B=W2[e], scale -> g_ya[m] fp16)
template<int MODE, int KDIM>
__global__ void __launch_bounds__(256) mma_gemm_kernel(
    const float* __restrict__ Ain, const float* __restrict__ Bin,
    const float* __restrict__ bias, float* __restrict__ Cout, int Ncols)
{
    constexpr bool A_HALF = (MODE != 1);
    constexpr int T = KDIM / 32;
    __shared__ unsigned As[2][128 * LDU];
    __shared__ unsigned Bs[2][128 * LDU];
    __shared__ int sm_pos[512];

    const int e = (MODE == 0) ? 0 : blockIdx.z;
    int bm, bn;
    const float* A = Ain;
    const __half* Ah = reinterpret_cast<const __half*>(Ain);
    const float* B = Bin;
    const float* bp = bias;
    int cnt = 0;
    if (MODE == 0) {
        bm = blockIdx.y * 128; bn = blockIdx.x * 128;
    } else {
        cnt = g_cnt[e];
        bm = blockIdx.y * 128;
        if (bm >= cnt) return;
        bn = blockIdx.x * 128;
        if (MODE == 1) {
            B = Bin + (size_t)e * RNK * KDIM;
            bp = bias + e * RNK;
        } else {
            Ah = reinterpret_cast<const __half*>(Ain) + (size_t)e * CAPV * RNK;
            B = Bin + (size_t)e * HIDV * RNK;
            bp = bias + (size_t)e * HIDV;
        }
    }

    const int tid = threadIdx.x;
    const float* Arow[4];
    const __half* Ahrow[4];
    const float* Brow[4];
    int soff[4];   // uint index: r*LDU + c/2
#pragma unroll
    for (int i = 0; i < 4; i++) {
        int idx = tid + i * 256;
        int r = idx >> 3;
        int c = (idx & 7) * 4;
        int grow;
        if (MODE == 1) grow = g_slot_tok[e * CAPV + bm + r];
        else grow = bm + r;
        if (A_HALF) Ahrow[i] = Ah + (size_t)grow * KDIM + c;
        else        Arow[i]  = A + (size_t)grow * KDIM + c;
        Brow[i] = B + (size_t)(bn + r) * KDIM + c;
        soff[i] = r * LDU + (c >> 1);
    }

    const int wid = tid >> 5, lane = tid & 31;
    const int wm = (wid & 1) * 64;
    const int wn = (wid >> 1) * 32;
    const int gid = lane >> 2, tg = lane & 3;

    uint32_t aBase = (uint32_t)__cvta_generic_to_shared(&As[0][0])
                   + (uint32_t)(wm + (lane & 7) + ((lane >> 3) & 1) * 8) * 80u
                   + ((lane >> 4) & 1) * 16u;
    uint32_t bBase = (uint32_t)__cvta_generic_to_shared(&Bs[0][0])
                   + (uint32_t)(wn + (lane >> 4) * 8 + (lane & 7)) * 80u
                   + ((lane >> 3) & 1) * 16u;

    float acc[4][4][4] = {};

    uint2  ua[4];
    float4 va[4], vb[4];
#pragma unroll
    for (int i = 0; i < 4; i++) {
        if (A_HALF) ua[i] = *(const uint2*)(Ahrow[i]);
        else        va[i] = *(const float4*)(Arow[i]);
        vb[i] = *(const float4*)(Brow[i]);
    }

    for (int t = 0; t < T; t++) {
        const int buf = t & 1;
        unsigned* as = As[buf];
        unsigned* bs = Bs[buf];
#pragma unroll
        for (int i = 0; i < 4; i++) {
            if (A_HALF) {
                as[soff[i]]     = ua[i].x;
                as[soff[i] + 1] = ua[i].y;
            } else {
                as[soff[i]]     = pkh2(va[i].x, va[i].y);
                as[soff[i] + 1] = pkh2(va[i].z, va[i].w);
            }
            bs[soff[i]]     = pkh2(vb[i].x, vb[i].y);
            bs[soff[i] + 1] = pkh2(vb[i].z, vb[i].w);
        }
        if (t + 1 < T) {
            int k0 = (t + 1) * 32;
#pragma unroll
            for (int i = 0; i < 4; i++) {
                if (A_HALF) ua[i] = *(const uint2*)(Ahrow[i] + k0);
                else        va[i] = *(const float4*)(Arow[i] + k0);
                vb[i] = *(const float4*)(Brow[i] + k0);
            }
        }
        __syncthreads();
        uint32_t aB = aBase + (uint32_t)buf * BUFB;
        uint32_t bB = bBase + (uint32_t)buf * BUFB;
#pragma unroll
        for (int ks = 0; ks < 2; ks++) {
            unsigned afr[4][4];
            unsigned bfr[4][2];
#pragma unroll
            for (int mi = 0; mi < 4; mi++)
                ldsm4(afr[mi][0], afr[mi][1], afr[mi][2], afr[mi][3],
                      aB + (uint32_t)mi * 1280u + (uint32_t)ks * 32u);
#pragma unroll
            for (int p = 0; p < 2; p++)
                ldsm4(bfr[2*p][0], bfr[2*p][1], bfr[2*p+1][0], bfr[2*p+1][1],
                      bB + (uint32_t)p * 1280u + (uint32_t)ks * 32u);
#pragma unroll
            for (int mi = 0; mi < 4; mi++)
#pragma unroll
                for (int ni = 0; ni < 4; ni++)
                    mma_f16(acc[mi][ni], afr[mi], bfr[ni]);
        }
    }

    if (MODE == 0) {
        for (int i = tid; i < 512; i += 256)
            sm_pos[i] = g_pos[(bm + (i >> 2)) * 4 + (i & 3)];
        __syncthreads();
    }

#pragma unroll
    for (int mi = 0; mi < 4; mi++) {
        int row0 = wm + mi * 16 + gid;
        int row1 = row0 + 8;
        if (MODE == 0) {
#pragma unroll
            for (int ni = 0; ni < 4; ni++) {
                int colg = bn + wn + ni * 8 + tg * 2;
                float2 bb = *(const float2*)&bp[colg];
                float v0 = acc[mi][ni][0] + bb.x;
                float v1 = acc[mi][ni][1] + bb.y;
                float v2 = acc[mi][ni][2] + bb.x;
                float v3 = acc[mi][ni][3] + bb.y;
#pragma unroll
                for (int k = 0; k < 4; k++) {
                    if (sm_pos[row0 * 4 + k] < CAPV) {
                        unsigned yw = *(const unsigned*)&g_ya[((size_t)((bm + row0) * 4 + k)) * HIDV + colg];
                        float2 yv = __half22float2(*reinterpret_cast<__half2*>(&yw));
                        v0 += yv.x; v1 += yv.y;
                    }
                    if (sm_pos[row1 * 4 + k] < CAPV) {
                        unsigned yw = *(const unsigned*)&g_ya[((size_t)((bm + row1) * 4 + k)) * HIDV + colg];
                        float2 yv = __half22float2(*reinterpret_cast<__half2*>(&yw));
                        v2 += yv.x; v3 += yv.y;
                    }
                }
                *(float2*)&Cout[(size_t)(bm + row0) * Ncols + colg] = make_float2(v0, v1);
                *(float2*)&Cout[(size_t)(bm + row1) * Ncols + colg] = make_float2(v2, v3);
            }
        } else if (MODE == 1) {
#pragma unroll
            for (int ni = 0; ni < 4; ni++) {
                int colg = bn + wn + ni * 8 + tg * 2;
                float2 bb = *(const float2*)&bp[colg];
                int cc0 = bm + row0, cc1 = bm + row1;
                if (cc0 < cnt) {
                    *(unsigned*)&g_h[((size_t)e * CAPV + cc0) * RNK + colg] =
                        pkh2(fmaxf(acc[mi][ni][0] + bb.x, 0.f), fmaxf(acc[mi][ni][1] + bb.y, 0.f));
                }
                if (cc1 < cnt) {
                    *(unsigned*)&g_h[((size_t)e * CAPV + cc1) * RNK + colg] =
                        pkh2(fmaxf(acc[mi][ni][2] + bb.x, 0.f), fmaxf(acc[mi][ni][3] + bb.y, 0.f));
                }
            }
        } else {
            int cc0 = bm + row0, cc1 = bm + row1;
            int m0 = -1, m1 = -1;
            float s0 = 0.f, s1 = 0.f;
            if (cc0 < cnt) { m0 = g_slot_m[e * CAPV + cc0]; s0 = g_slot_s[e * CAPV + cc0]; }
            if (cc1 < cnt) { m1 = g_slot_m[e * CAPV + cc1]; s1 = g_slot_s[e * CAPV + cc1]; }
#pragma unroll
            for (int ni = 0; ni < 4; ni++) {
                int colg = bn + wn + ni * 8 + tg * 2;
                float2 bb = *(const float2*)&bp[colg];
                if (m0 >= 0)
                    *(unsigned*)&g_ya[(size_t)m0 * HIDV + colg] =
                        pkh2(s0 * (acc[mi][ni][0] + bb.x), s0 * (acc[mi][ni][1] + bb.y));
                if (m1 >= 0)
                    *(unsigned*)&g_ya[(size_t)m1 * HIDV + colg] =
                        pkh2(s1 * (acc[mi][ni][2] + bb.x), s1 * (acc[mi][ni][3] + bb.y));
            }
        }
    }
}

// ---------------- LoRA-up OVERFLOW: rows 128..cnt in 32-row tiles (early-exit grid) --------
__global__ void __launch_bounds__(256) gemm2ov_kernel(
    const float* __restrict__ Bin, const float* __restrict__ bias)
{
    __shared__ unsigned As[2][32 * LDU];
    __shared__ unsigned Bs[2][128 * LDU];

    const int e = blockIdx.z;
    const int cnt = g_cnt[e];
    const int bm = 128 + blockIdx.y * 32;
    if (bm >= cnt) return;
    const int bn = blockIdx.x * 128;
    const __half* Ah = g_h + (size_t)e * CAPV * RNK;
    const float* B = Bin + (size_t)e * HIDV * RNK;
    const float* bp = bias + (size_t)e * HIDV;

    const int tid = threadIdx.x;
    const int rA = tid >> 3;
    const int cA = (tid & 7) * 4;
    const __half* Ahrow = Ah + (size_t)(bm + rA) * RNK + cA;
    const int soffA = rA * LDU + (cA >> 1);
    const float* Brow[4];
    int soffB[4];
#pragma unroll
    for (int i = 0; i < 4; i++) {
        int idx = tid + i * 256;
        int r = idx >> 3;
        int c = (idx & 7) * 4;
        Brow[i] = B + (size_t)(bn + r) * RNK + c;
        soffB[i] = r * LDU + (c >> 1);
    }

    const int wid = tid >> 5, lane = tid & 31;
    const int wm = (wid & 1) * 16;
    const int wn = (wid >> 1) * 32;
    const int gid = lane >> 2, tg = lane & 3;

    uint32_t aBase = (uint32_t)__cvta_generic_to_shared(&As[0][0])
                   + (uint32_t)(wm + (lane & 7) + ((lane >> 3) & 1) * 8) * 80u
                   + ((lane >> 4) & 1) * 16u;
    uint32_t bBase = (uint32_t)__cvta_generic_to_shared(&Bs[0][0])
                   + (uint32_t)(wn + (lane >> 4) * 8 + (lane & 7)) * 80u
                   + ((lane >> 3) & 1) * 16u;

    float acc[4][4] = {};

    uint2 ua = *(const uint2*)(Ahrow);
    float4 vb[4];
#pragma unroll
    for (int i = 0; i < 4; i++) vb[i] = *(const float4*)(Brow[i]);

    for (int t = 0; t < 4; t++) {
        const int buf = t & 1;
        unsigned* as = As[buf];
        unsigned* bs = Bs[buf];
        as[soffA]     = ua.x;
        as[soffA + 1] = ua.y;
#pragma unroll
        for (int i = 0; i < 4; i++) {
            bs[soffB[i]]     = pkh2(vb[i].x, vb[i].y);
            bs[soffB[i] + 1] = pkh2(vb[i].z, vb[i].w);
        }
        if (t + 1 < 4) {
            int k0 = (t + 1) * 32;
            ua = *(const uint2*)(Ahrow + k0);
#pragma unroll
            for (int i = 0; i < 4; i++) vb[i] = *(const float4*)(Brow[i] + k0);
        }
        __syncthreads();
        uint32_t aB = aBase + (uint32_t)buf * ABUFB;
        uint32_t bB = bBase + (uint32_t)buf * BUFB;
#pragma unroll
        for (int ks = 0; ks < 2; ks++) {
            unsigned afr[4];
            unsigned bfr[4][2];
            ldsm4(afr[0], afr[1], afr[2], afr[3], aB + (uint32_t)ks * 32u);
#pragma unroll
            for (int p = 0; p < 2; p++)
                ldsm4(bfr[2*p][0], bfr[2*p][1], bfr[2*p+1][0], bfr[2*p+1][1],
                      bB + (uint32_t)p * 1280u + (uint32_t)ks * 32u);
#pragma unroll
            for (int ni = 0; ni < 4; ni++)
                mma_f16(acc[ni], afr, bfr[ni]);
        }
    }

    int row0 = wm + gid;
    int row1 = row0 + 8;
    int cc0 = bm + row0, cc1 = bm + row1;
    int m0 = -1, m1 = -1;
    float s0 = 0.f, s1 = 0.f;
    if (cc0 < cnt) { m0 = g_slot_m[e * CAPV + cc0]; s0 = g_slot_s[e * CAPV + cc0]; }
    if (cc1 < cnt) { m1 = g_slot_m[e * CAPV + cc1]; s1 = g_slot_s[e * CAPV + cc1]; }
#pragma unroll
    for (int ni = 0; ni < 4; ni++) {
        int colg = bn + wn + ni * 8 + tg * 2;
        float2 bb = *(const float2*)&bp[colg];
        if (m0 >= 0)
            *(unsigned*)&g_ya[(size_t)m0 * HIDV + colg] =
                pkh2(s0 * (acc[ni][0] + bb.x), s0 * (acc[ni][1] + bb.y));
        if (m1 >= 0)
            *(unsigned*)&g_ya[(size_t)m1 * HIDV + colg] =
                pkh2(s1 * (acc[ni][2] + bb.x), s1 * (acc[ni][3] + bb.y));
    }
}

// ---------------- host ----------------
extern "C" void kernel_launch(void* const* d_in, const int* in_sizes, int n_in,
                              void* d_out, int out_size) {
    const float* x    = (const float*)d_in[0];
    const float* Wr   = (const float*)d_in[1];
    const float* br   = (const float*)d_in[2];
    const float* diag = (const float*)d_in[3];
    const float* Wp   = (const float*)d_in[4];
    const float* bp   = (const float*)d_in[5];
    const float* W1   = (const float*)d_in[6];
    const float* b1   = (const float*)d_in[7];
    const float* W2   = (const float*)d_in[8];
    const float* b2   = (const float*)d_in[9];
    float* out = (float*)d_out;

    float* p_logits = nullptr;
    void* p_xeff = nullptr;
    void* p_h = nullptr;
    cudaGetSymbolAddress((void**)&p_logits, g_logits);
    cudaGetSymbolAddress(&p_xeff, g_xeff);
    cudaGetSymbolAddress(&p_h, g_h);

    init_kernel<<<1, 256>>>();

    // router logits (exact fp32 — discrete decisions depend on these)
    router_kernel<<<dim3(NE / 64, N_TOK / 64), 256>>>(x, Wr, br, p_logits);

    // exact order statistic a[419430] of |logits|:
    // two 8-bit radix passes, then collect + 2-level resolve of the low 16 bits
    hist24_kernel<<<512, 256>>>();
    pick_kernel<<<1, 256>>>();
    hist16_kernel<<<512, 256>>>();
    pick_kernel<<<1, 256>>>();
    collect_kernel<<<512, 256>>>();
    final_pick_kernel<<<1, 256>>>();

    topk_xeff_kernel<<<N_TOK / 4, 128>>>(x, diag);
    pos_kernel<<<NE, 256>>>();

    // LoRA down: h = relu(x_gathered @ W1^T + b1) -> fp16 (all slots; 2 x 128-row tiles)
    mma_gemm_kernel<1, DIMV><<<dim3(1, CAPV / 128, NE), 256>>>(x, W1, b1, nullptr, RNK);

    // LoRA up main: rows 0..127 per expert
    mma_gemm_kernel<2, RNK><<<dim3(HIDV / 128, 1, NE), 256>>>((const float*)p_h, W2, b2, nullptr, HIDV);

    // LoRA up overflow: rows 128..cnt in 32-row tiles (most blocks exit immediately)
    gemm2ov_kernel<<<dim3(HIDV / 128, 4, NE), 256>>>(W2, b2);

    // diag path + fused combine: out = xeff @ Wp^T + bp + sum_k ya[4n+k]
    mma_gemm_kernel<0, DIMV><<<dim3(HIDV / 128, N_TOK / 128), 256>>>((const float*)p_xeff, Wp, bp, out, HIDV);
}

// round 17
// speedup vs baseline: 1.0335x; 1.0069x over previous
#include <cuda_runtime.h>
#include <cuda_fp16.h>
#include <math.h>
#include <stdint.h>

#define N_TOK 4096
#define DIMV 1024
#define HIDV 4096
#define NE 128
#define TOPKV 4
#define RNK 128
#define CAPV 256
#define M_ASSIGN (N_TOK*TOPKV)
#define LDU 20            // smem row stride in uints (40 halves = 80 bytes): conflict-free
#define BUFB (128*LDU*4)  // bytes per 128-row smem buffer (10240)
#define ABUFB (32*LDU*4)  // bytes per 32-row smem buffer (2560)
#define NCAND 16384       // candidate buffer (expected ~1.8K sharing 16-bit prefix)
#define RANK0 419430u     // floor(0.8 * (N-1)), N = 524288

// ---------------- device scratch (static, zero-init at module load; self-restoring) --------
__device__ float  g_logits[N_TOK*NE];               // 2 MB
__device__ __half g_xeff[N_TOK*DIMV];               // 8 MB
__device__ __half g_h[NE*CAPV*RNK];                 // 8 MB
__device__ __half g_ya[(size_t)M_ASSIGN*HIDV];      // 128 MB, assignment-major LoRA outputs
__device__ int    g_topi[M_ASSIGN];
__device__ float  g_scores[M_ASSIGN];
__device__ int    g_pos[M_ASSIGN];
__device__ int    g_slot_tok[NE*CAPV];
__device__ int    g_slot_m[NE*CAPV];
__device__ float  g_slot_s[NE*CAPV];
__device__ int    g_cnt[NE];
__device__ unsigned g_histA[256];    // top-8-bit histogram (zeroed by final_pick each run)
__device__ unsigned g_histB[256];    // bits[16:24) histogram (zeroed by final_pick each run)
__device__ unsigned g_cand[NCAND];
__device__ int    g_ncand;           // reset by final_pick each run
__device__ float  g_thr;

__device__ __forceinline__ unsigned pkh2(float lo, float hi) {
    __half2 h = __floats2half2_rn(lo, hi);
    return *reinterpret_cast<unsigned*>(&h);
}

__device__ __forceinline__ void mma_f16(float* d, const unsigned* a, const unsigned* b) {
    asm volatile(
        "mma.sync.aligned.m16n8k16.row.col.f32.f16.f16.f32 "
        "{%0,%1,%2,%3}, {%4,%5,%6,%7}, {%8,%9}, {%0,%1,%2,%3};"
        : "+f"(d[0]), "+f"(d[1]), "+f"(d[2]), "+f"(d[3])
        : "r"(a[0]), "r"(a[1]), "r"(a[2]), "r"(a[3]), "r"(b[0]), "r"(b[1]));
}

__device__ __forceinline__ void ldsm4(unsigned& r0, unsigned& r1, unsigned& r2, unsigned& r3,
                                      uint32_t addr) {
    asm volatile("ldmatrix.sync.aligned.m8n8.x4.shared.b16 {%0,%1,%2,%3}, [%4];"
                 : "=r"(r0), "=r"(r1), "=r"(r2), "=r"(r3) : "r"(addr));
}

// block-wide (256 threads) scan over a 256-bin histogram; returns (selected bin, sub-rank).
// Deterministic recompute — every block gets the same answer from the same global data.
__device__ __forceinline__ uint2 scan_pick(const unsigned* hist, unsigned rank,
                                           unsigned* ws, unsigned* sel) {
    int tid = threadIdx.x;
    int lane = tid & 31, warp = tid >> 5;
    __syncthreads();                 // protect ws/sel from previous use
    unsigned c = hist[tid];
    unsigned v = c;
#pragma unroll
    for (int off = 1; off < 32; off <<= 1) {
        unsigned o = __shfl_up_sync(0xffffffffu, v, off);
        if (lane >= off) v += o;
    }
    if (lane == 31) ws[warp] = v;
    __syncthreads();
    unsigned woff = 0;
#pragma unroll
    for (int w = 0; w < 8; w++)
        if (w < warp) woff += ws[w];
    unsigned inc = v + woff;
    unsigned exc = inc - c;
    if (rank >= exc && rank < inc) { sel[0] = (unsigned)tid; sel[1] = rank - exc; }
    __syncthreads();
    return make_uint2(sel[0], sel[1]);
}

// ---------------- router: fp32 SIMT 64x64 tiles (exact decisions) + fused top-8 hist -------
__global__ void __launch_bounds__(256) router_kernel(
    const float* __restrict__ A, const float* __restrict__ B,
    const float* __restrict__ bias, float* __restrict__ C)
{
    const int K = DIMV, N = NE;
    __shared__ float As[16][68];
    __shared__ float Bs[16][68];
    __shared__ unsigned hh[8][256];
    int bm = blockIdx.y * 64, bn = blockIdx.x * 64;
    int tid = threadIdx.x;
    int warp8 = tid >> 5;
    int lr = tid >> 2;
    int lc = (tid & 3) * 4;
    int tx = tid & 15, ty = tid >> 4;
    for (int i = tid; i < 2048; i += 256) ((unsigned*)hh)[i] = 0u;
    const float* Ap = A + (size_t)(bm + lr) * K + lc;
    const float* Bp = B + (size_t)(bn + lr) * K + lc;
    float acc[4][4] = {};
    for (int k0 = 0; k0 < K; k0 += 16) {
        float4 a4 = *(const float4*)(Ap + k0);
        float4 b4 = *(const float4*)(Bp + k0);
        __syncthreads();
        As[lc + 0][lr] = a4.x; As[lc + 1][lr] = a4.y; As[lc + 2][lr] = a4.z; As[lc + 3][lr] = a4.w;
        Bs[lc + 0][lr] = b4.x; Bs[lc + 1][lr] = b4.y; Bs[lc + 2][lr] = b4.z; Bs[lc + 3][lr] = b4.w;
        __syncthreads();
#pragma unroll
        for (int kk = 0; kk < 16; kk++) {
            float4 av = *(const float4*)&As[kk][ty * 4];
            float4 bv = *(const float4*)&Bs[kk][tx * 4];
            float a[4] = { av.x, av.y, av.z, av.w };
            float b[4] = { bv.x, bv.y, bv.z, bv.w };
#pragma unroll
            for (int i = 0; i < 4; i++)
#pragma unroll
                for (int j = 0; j < 4; j++)
                    acc[i][j] += a[i] * b[j];
        }
    }
    float4 bb = *(const float4*)&bias[bn + tx * 4];
    float b[4] = { bb.x, bb.y, bb.z, bb.w };
#pragma unroll
    for (int i = 0; i < 4; i++) {
        float v[4];
#pragma unroll
        for (int j = 0; j < 4; j++) v[j] = acc[i][j] + b[j];
        float* cp = C + (size_t)(bm + ty * 4 + i) * N + bn + tx * 4;
        *(float4*)cp = make_float4(v[0], v[1], v[2], v[3]);
#pragma unroll
        for (int j = 0; j < 4; j++) {
            unsigned u = __float_as_uint(fabsf(v[j]));
            atomicAdd(&hh[warp8][u >> 24], 1u);
        }
    }
    __syncthreads();
    unsigned s = 0;
#pragma unroll
    for (int w = 0; w < 8; w++) s += hh[w][tid];
    if (s) atomicAdd(&g_histA[tid], s);
}

// ---------------- hist pass 2: bits [16:24) filtered by recomputed top-8 prefix ------------
__global__ void __launch_bounds__(256) hist16_kernel() {
    __shared__ unsigned h[256];
    __shared__ unsigned ws[8];
    __shared__ unsigned sel[2];
    int tid = threadIdx.x;
    h[tid] = 0u;
    uint2 p1 = scan_pick(g_histA, RANK0, ws, sel);
    unsigned prefix = p1.x;
#pragma unroll
    for (int j = 0; j < 4; j++) {
        int idx = (blockIdx.x * 4 + j) * 256 + tid;
        unsigned u = __float_as_uint(fabsf(g_logits[idx]));
        if ((u >> 24) == prefix) atomicAdd(&h[(u >> 16) & 255], 1u);
    }
    __syncthreads();
    if (h[tid]) atomicAdd(&g_histB[tid], h[tid]);
}

// ---------------- collect values sharing the recomputed 16-bit prefix ----------------------
__global__ void __launch_bounds__(256) collect_kernel() {
    __shared__ unsigned ws[8];
    __shared__ unsigned sel[2];
    int tid = threadIdx.x;
    uint2 p1 = scan_pick(g_histA, RANK0, ws, sel);
    uint2 p2 = scan_pick(g_histB, p1.y, ws, sel);
    unsigned pfx16 = (p1.x << 8) | p2.x;
#pragma unroll
    for (int j = 0; j < 4; j++) {
        int idx = (blockIdx.x * 4 + j) * 256 + tid;
        unsigned u = __float_as_uint(fabsf(g_logits[idx]));
        if ((u >> 16) == pfx16) {
            int p = atomicAdd(&g_ncand, 1);
            if (p < NCAND) g_cand[p] = u;
        }
    }
}

// ---------------- resolve low 16 bits among candidates; restore select state ---------------
__global__ void __launch_bounds__(256) final_pick_kernel() {
    __shared__ unsigned h[256];
    __shared__ unsigned ws[8];
    __shared__ unsigned sel[2];
    int tid = threadIdx.x;
    uint2 p1 = scan_pick(g_histA, RANK0, ws, sel);
    uint2 p2 = scan_pick(g_histB, p1.y, ws, sel);
    unsigned pfx16 = (p1.x << 8) | p2.x;
    unsigned rank2 = p2.y;
    int n = g_ncand;
    if (n > NCAND) n = NCAND;
    // level A: bits [8:16)
    h[tid] = 0u;
    __syncthreads();
    for (int i = tid; i < n; i += 256) atomicAdd(&h[(g_cand[i] >> 8) & 255], 1u);
    uint2 pa = scan_pick(h, rank2, ws, sel);
    unsigned selA = pa.x;
    unsigned rank3 = pa.y;
    // level B: bits [0:8) filtered
    __syncthreads();
    h[tid] = 0u;
    __syncthreads();
    for (int i = tid; i < n; i += 256) {
        unsigned u = g_cand[i];
        if (((u >> 8) & 255) == selA) atomicAdd(&h[u & 255], 1u);
    }
    uint2 pb = scan_pick(h, rank3, ws, sel);
    if (tid == 0) {
        g_thr = __uint_as_float((pfx16 << 16) | (selA << 8) | pb.x);
        g_ncand = 0;                 // restore for next graph replay
    }
    g_histA[tid] = 0u;
    g_histB[tid] = 0u;
}

// ---------------- fused top-4 + softmax + xeff (one warp per token; fp16 xeff out) ---------
__global__ void __launch_bounds__(128) topk_xeff_kernel(const float* __restrict__ x,
                                                        const float* __restrict__ diag) {
    int warp = threadIdx.x >> 5;
    int lane = threadIdx.x & 31;
    int n = blockIdx.x * 4 + warp;
    float thr = g_thr;
    const float* row = g_logits + (size_t)n * NE;
    float v[4]; int idx[4];
#pragma unroll
    for (int j = 0; j < 4; j++) {
        int e = lane + j * 32;
        float xv = row[e];
        if (fabsf(xv) < thr) xv = 0.0f;
        v[j] = xv; idx[j] = e;
    }
    float tv[4]; int ti[4];
#pragma unroll
    for (int sel = 0; sel < 4; sel++) {
        float bv = v[0]; int bi = idx[0];
#pragma unroll
        for (int j = 1; j < 4; j++)
            if (v[j] > bv || (v[j] == bv && idx[j] < bi)) { bv = v[j]; bi = idx[j]; }
#pragma unroll
        for (int off = 16; off; off >>= 1) {
            float ov = __shfl_xor_sync(0xffffffffu, bv, off);
            int   oi = __shfl_xor_sync(0xffffffffu, bi, off);
            if (ov > bv || (ov == bv && oi < bi)) { bv = ov; bi = oi; }
        }
        tv[sel] = bv; ti[sel] = bi;   // warp-uniform after reduction
#pragma unroll
        for (int j = 0; j < 4; j++)
            if (idx[j] == bi) v[j] = -INFINITY;
    }
    float m = tv[0];
    float ex[4], sum = 0.0f;
#pragma unroll
    for (int k = 0; k < 4; k++) { ex[k] = expf(tv[k] - m); sum += ex[k]; }
    float s[4];
#pragma unroll
    for (int k = 0; k < 4; k++) s[k] = ex[k] / sum;
    if (lane < 4) {
        g_topi[n * 4 + lane] = ti[lane];
        g_scores[n * 4 + lane] = s[lane];
    }
    const float* d0 = diag + (size_t)ti[0] * DIMV;
    const float* d1 = diag + (size_t)ti[1] * DIMV;
    const float* d2 = diag + (size_t)ti[2] * DIMV;
    const float* d3 = diag + (size_t)ti[3] * DIMV;
    const float* xr = x + (size_t)n * DIMV;
    __half* xe = g_xeff + (size_t)n * DIMV;
#pragma unroll
    for (int it = 0; it < 8; it++) {
        int d = lane * 4 + it * 128;
        float4 a = *(const float4*)&d0[d];
        float4 b = *(const float4*)&d1[d];
        float4 c = *(const float4*)&d2[d];
        float4 e = *(const float4*)&d3[d];
        float4 xv = *(const float4*)&xr[d];
        float ox = xv.x * (s[0]*a.x + s[1]*b.x + s[2]*c.x + s[3]*e.x);
        float oy = xv.y * (s[0]*a.y + s[1]*b.y + s[2]*c.y + s[3]*e.y);
        float oz = xv.z * (s[0]*a.z + s[1]*b.z + s[2]*c.z + s[3]*e.z);
        float ow = xv.w * (s[0]*a.w + s[1]*b.w + s[2]*c.w + s[3]*e.w);
        *(uint2*)&xe[d] = make_uint2(pkh2(ox, oy), pkh2(oz, ow));
    }
}

// ---------------- deterministic capacity positions (ballot scan, matches cumsum order) -----
__global__ void __launch_bounds__(256) pos_kernel() {
    int e = blockIdx.x;
    int tid = threadIdx.x;
    int lane = tid & 31, warp = tid >> 5;
    __shared__ int swc[8];
    int base = 0;
    for (int chunk = 0; chunk < M_ASSIGN / 256; chunk++) {
        int m = chunk * 256 + tid;
        int flag = (g_topi[m] == e) ? 1 : 0;
        unsigned mask = __ballot_sync(0xffffffffu, flag);
        int wcnt = __popc(mask);
        int wpre = __popc(mask & ((1u << lane) - 1u));
        if (lane == 0) swc[warp] = wcnt;
        __syncthreads();
        int woff = 0, tot = 0;
#pragma unroll
        for (int w = 0; w < 8; w++) {
            int cw = swc[w];
            if (w < warp) woff += cw;
            tot += cw;
        }
        if (flag) {
            int pos = base + woff + wpre;
            g_pos[m] = pos;
            if (pos < CAPV) {
                g_slot_tok[e * CAPV + pos] = m >> 2;
                g_slot_m[e * CAPV + pos] = m;
                g_slot_s[e * CAPV + pos] = g_scores[m];
            }
        }
        base += tot;
        __syncthreads();
    }
    if (tid == 0) g_cnt[e] = (base < CAPV) ? base : CAPV;
}

// ---------------- fp16 tensor-core GEMM family (pipelined, double-buffered) ----------------
// MODE 0: diag path + fused LoRA combine (A=g_xeff fp16, B=Wp, bias=bp, C=out)
// MODE 1: LoRA down (A=x fp32 gathered, B=W1[e], bias=b1[e], relu -> g_h fp16)
// MODE 2: LoRA up, rows 0..127 (A=g_h[e] fp16, B=W2[e], scale -> g_ya[m] fp16)
template<int MODE, int KDIM>
__global__ void __launch_bounds__(256) mma_gemm_kernel(
    const float* __restrict__ Ain, const float* __restrict__ Bin,
    const float* __restrict__ bias, float* __restrict__ Cout, int Ncols)
{
    constexpr bool A_HALF = (MODE != 1);
    constexpr int T = KDIM / 32;
    __shared__ unsigned As[2][128 * LDU];
    __shared__ unsigned Bs[2][128 * LDU];
    __shared__ int sm_pos[512];

    const int e = (MODE == 0) ? 0 : blockIdx.z;
    int bm, bn;
    const float* A = Ain;
    const __half* Ah = reinterpret_cast<const __half*>(Ain);
    const float* B = Bin;
    const float* bp = bias;
    int cnt = 0;
    if (MODE == 0) {
        bm = blockIdx.y * 128; bn = blockIdx.x * 128;
    } else {
        cnt = g_cnt[e];
        bm = blockIdx.y * 128;
        if (bm >= cnt) return;
        bn = blockIdx.x * 128;
        if (MODE == 1) {
            B = Bin + (size_t)e * RNK * KDIM;
            bp = bias + e * RNK;
        } else {
            Ah = reinterpret_cast<const __half*>(Ain) + (size_t)e * CAPV * RNK;
            B = Bin + (size_t)e * HIDV * RNK;
            bp = bias + (size_t)e * HIDV;
        }
    }

    const int tid = threadIdx.x;
    const float* Arow[4];
    const __half* Ahrow[4];
    const float* Brow[4];
    int soff[4];   // uint index: r*LDU + c/2
#pragma unroll
    for (int i = 0; i < 4; i++) {
        int idx = tid + i * 256;
        int r = idx >> 3;
        int c = (idx & 7) * 4;
        int grow;
        if (MODE == 1) grow = g_slot_tok[e * CAPV + bm + r];
        else grow = bm + r;
        if (A_HALF) Ahrow[i] = Ah + (size_t)grow * KDIM + c;
        else        Arow[i]  = A + (size_t)grow * KDIM + c;
        Brow[i] = B + (size_t)(bn + r) * KDIM + c;
        soff[i] = r * LDU + (c >> 1);
    }

    const int wid = tid >> 5, lane = tid & 31;
    const int wm = (wid & 1) * 64;
    const int wn = (wid >> 1) * 32;
    const int gid = lane >> 2, tg = lane & 3;

    uint32_t aBase = (uint32_t)__cvta_generic_to_shared(&As[0][0])
                   + (uint32_t)(wm + (lane & 7) + ((lane >> 3) & 1) * 8) * 80u
                   + ((lane >> 4) & 1) * 16u;
    uint32_t bBase = (uint32_t)__cvta_generic_to_shared(&Bs[0][0])
                   + (uint32_t)(wn + (lane >> 4) * 8 + (lane & 7)) * 80u
                   + ((lane >> 3) & 1) * 16u;

    float acc[4][4][4] = {};

    uint2  ua[4];
    float4 va[4], vb[4];
#pragma unroll
    for (int i = 0; i < 4; i++) {
        if (A_HALF) ua[i] = *(const uint2*)(Ahrow[i]);
        else        va[i] = *(const float4*)(Arow[i]);
        vb[i] = *(const float4*)(Brow[i]);
    }

    for (int t = 0; t < T; t++) {
        const int buf = t & 1;
        unsigned* as = As[buf];
        unsigned* bs = Bs[buf];
#pragma unroll
        for (int i = 0; i < 4; i++) {
            if (A_HALF) {
                as[soff[i]]     = ua[i].x;
                as[soff[i] + 1] = ua[i].y;
            } else {
                as[soff[i]]     = pkh2(va[i].x, va[i].y);
                as[soff[i] + 1] = pkh2(va[i].z, va[i].w);
            }
            bs[soff[i]]     = pkh2(vb[i].x, vb[i].y);
            bs[soff[i] + 1] = pkh2(vb[i].z, vb[i].w);
        }
        if (t + 1 < T) {
            int k0 = (t + 1) * 32;
#pragma unroll
            for (int i = 0; i < 4; i++) {
                if (A_HALF) ua[i] = *(const uint2*)(Ahrow[i] + k0);
                else        va[i] = *(const float4*)(Arow[i] + k0);
                vb[i] = *(const float4*)(Brow[i] + k0);
            }
        }
        __syncthreads();
        uint32_t aB = aBase + (uint32_t)buf * BUFB;
        uint32_t bB = bBase + (uint32_t)buf * BUFB;
#pragma unroll
        for (int ks = 0; ks < 2; ks++) {
            unsigned afr[4][4];
            unsigned bfr[4][2];
#pragma unroll
            for (int mi = 0; mi < 4; mi++)
                ldsm4(afr[mi][0], afr[mi][1], afr[mi][2], afr[mi][3],
                      aB + (uint32_t)mi * 1280u + (uint32_t)ks * 32u);
#pragma unroll
            for (int p = 0; p < 2; p++)
                ldsm4(bfr[2*p][0], bfr[2*p][1], bfr[2*p+1][0], bfr[2*p+1][1],
                      bB + (uint32_t)p * 1280u + (uint32_t)ks * 32u);
#pragma unroll
            for (int mi = 0; mi < 4; mi++)
#pragma unroll
                for (int ni = 0; ni < 4; ni++)
                    mma_f16(acc[mi][ni], afr[mi], bfr[ni]);
        }
    }

    if (MODE == 0) {
        for (int i = tid; i < 512; i += 256)
            sm_pos[i] = g_pos[(bm + (i >> 2)) * 4 + (i & 3)];
        __syncthreads();
    }

#pragma unroll
    for (int mi = 0; mi < 4; mi++) {
        int row0 = wm + mi * 16 + gid;
        int row1 = row0 + 8;
        if (MODE == 0) {
#pragma unroll
            for (int ni = 0; ni < 4; ni++) {
                int colg = bn + wn + ni * 8 + tg * 2;
                float2 bb = *(const float2*)&bp[colg];
                float v0 = acc[mi][ni][0] + bb.x;
                float v1 = acc[mi][ni][1] + bb.y;
                float v2 = acc[mi][ni][2] + bb.x;
                float v3 = acc[mi][ni][3] + bb.y;
#pragma unroll
                for (int k = 0; k < 4; k++) {
                    if (sm_pos[row0 * 4 + k] < CAPV) {
                        unsigned yw = *(const unsigned*)&g_ya[((size_t)((bm + row0) * 4 + k)) * HIDV + colg];
                        float2 yv = __half22float2(*reinterpret_cast<__half2*>(&yw));
                        v0 += yv.x; v1 += yv.y;
                    }
                    if (sm_pos[row1 * 4 + k] < CAPV) {
                        unsigned yw = *(const unsigned*)&g_ya[((size_t)((bm + row1) * 4 + k)) * HIDV + colg];
                        float2 yv = __half22float2(*reinterpret_cast<__half2*>(&yw));
                        v2 += yv.x; v3 += yv.y;
                    }
                }
                *(float2*)&Cout[(size_t)(bm + row0) * Ncols + colg] = make_float2(v0, v1);
                *(float2*)&Cout[(size_t)(bm + row1) * Ncols + colg] = make_float2(v2, v3);
            }
        } else if (MODE == 1) {
#pragma unroll
            for (int ni = 0; ni < 4; ni++) {
                int colg = bn + wn + ni * 8 + tg * 2;
                float2 bb = *(const float2*)&bp[colg];
                int cc0 = bm + row0, cc1 = bm + row1;
                if (cc0 < cnt) {
                    *(unsigned*)&g_h[((size_t)e * CAPV + cc0) * RNK + colg] =
                        pkh2(fmaxf(acc[mi][ni][0] + bb.x, 0.f), fmaxf(acc[mi][ni][1] + bb.y, 0.f));
                }
                if (cc1 < cnt) {
                    *(unsigned*)&g_h[((size_t)e * CAPV + cc1) * RNK + colg] =
                        pkh2(fmaxf(acc[mi][ni][2] + bb.x, 0.f), fmaxf(acc[mi][ni][3] + bb.y, 0.f));
                }
            }
        } else {
            int cc0 = bm + row0, cc1 = bm + row1;
            int m0 = -1, m1 = -1;
            float s0 = 0.f, s1 = 0.f;
            if (cc0 < cnt) { m0 = g_slot_m[e * CAPV + cc0]; s0 = g_slot_s[e * CAPV + cc0]; }
            if (cc1 < cnt) { m1 = g_slot_m[e * CAPV + cc1]; s1 = g_slot_s[e * CAPV + cc1]; }
#pragma unroll
            for (int ni = 0; ni < 4; ni++) {
                int colg = bn + wn + ni * 8 + tg * 2;
                float2 bb = *(const float2*)&bp[colg];
                if (m0 >= 0)
                    *(unsigned*)&g_ya[(size_t)m0 * HIDV + colg] =
                        pkh2(s0 * (acc[mi][ni][0] + bb.x), s0 * (acc[mi][ni][1] + bb.y));
                if (m1 >= 0)
                    *(unsigned*)&g_ya[(size_t)m1 * HIDV + colg] =
                        pkh2(s1 * (acc[mi][ni][2] + bb.x), s1 * (acc[mi][ni][3] + bb.y));
            }
        }
    }
}

// ---------------- LoRA-up OVERFLOW: rows 128..cnt in 32-row tiles (early-exit grid) --------
__global__ void __launch_bounds__(256) gemm2ov_kernel(
    const float* __restrict__ Bin, const float* __restrict__ bias)
{
    __shared__ unsigned As[2][32 * LDU];
    __shared__ unsigned Bs[2][128 * LDU];

    const int e = blockIdx.z;
    const int cnt = g_cnt[e];
    const int bm = 128 + blockIdx.y * 32;
    if (bm >= cnt) return;
    const int bn = blockIdx.x * 128;
    const __half* Ah = g_h + (size_t)e * CAPV * RNK;
    const float* B = Bin + (size_t)e * HIDV * RNK;
    const float* bp = bias + (size_t)e * HIDV;

    const int tid = threadIdx.x;
    const int rA = tid >> 3;
    const int cA = (tid & 7) * 4;
    const __half* Ahrow = Ah + (size_t)(bm + rA) * RNK + cA;
    const int soffA = rA * LDU + (cA >> 1);
    const float* Brow[4];
    int soffB[4];
#pragma unroll
    for (int i = 0; i < 4; i++) {
        int idx = tid + i * 256;
        int r = idx >> 3;
        int c = (idx & 7) * 4;
        Brow[i] = B + (size_t)(bn + r) * RNK + c;
        soffB[i] = r * LDU + (c >> 1);
    }

    const int wid = tid >> 5, lane = tid & 31;
    const int wm = (wid & 1) * 16;
    const int wn = (wid >> 1) * 32;
    const int gid = lane >> 2, tg = lane & 3;

    uint32_t aBase = (uint32_t)__cvta_generic_to_shared(&As[0][0])
                   + (uint32_t)(wm + (lane & 7) + ((lane >> 3) & 1) * 8) * 80u
                   + ((lane >> 4) & 1) * 16u;
    uint32_t bBase = (uint32_t)__cvta_generic_to_shared(&Bs[0][0])
                   + (uint32_t)(wn + (lane >> 4) * 8 + (lane & 7)) * 80u
                   + ((lane >> 3) & 1) * 16u;

    float acc[4][4] = {};

    uint2 ua = *(const uint2*)(Ahrow);
    float4 vb[4];
#pragma unroll
    for (int i = 0; i < 4; i++) vb[i] = *(const float4*)(Brow[i]);

    for (int t = 0; t < 4; t++) {
        const int buf = t & 1;
        unsigned* as = As[buf];
        unsigned* bs = Bs[buf];
        as[soffA]     = ua.x;
        as[soffA + 1] = ua.y;
#pragma unroll
        for (int i = 0; i < 4; i++) {
            bs[soffB[i]]     = pkh2(vb[i].x, vb[i].y);
            bs[soffB[i] + 1] = pkh2(vb[i].z, vb[i].w);
        }
        if (t + 1 < 4) {
            int k0 = (t + 1) * 32;
            ua = *(const uint2*)(Ahrow + k0);
#pragma unroll
            for (int i = 0; i < 4; i++) vb[i] = *(const float4*)(Brow[i] + k0);
        }
        __syncthreads();
        uint32_t aB = aBase + (uint32_t)buf * ABUFB;
        uint32_t bB = bBase + (uint32_t)buf * BUFB;
#pragma unroll
        for (int ks = 0; ks < 2; ks++) {
            unsigned afr[4];
            unsigned bfr[4][2];
            ldsm4(afr[0], afr[1], afr[2], afr[3], aB + (uint32_t)ks * 32u);
#pragma unroll
            for (int p = 0; p < 2; p++)
                ldsm4(bfr[2*p][0], bfr[2*p][1], bfr[2*p+1][0], bfr[2*p+1][1],
                      bB + (uint32_t)p * 1280u + (uint32_t)ks * 32u);
#pragma unroll
            for (int ni = 0; ni < 4; ni++)
                mma_f16(acc[ni], afr, bfr[ni]);
        }
    }

    int row0 = wm + gid;
    int row1 = row0 + 8;
    int cc0 = bm + row0, cc1 = bm + row1;
    int m0 = -1, m1 = -1;
    float s0 = 0.f, s1 = 0.f;
    if (cc0 < cnt) { m0 = g_slot_m[e * CAPV + cc0]; s0 = g_slot_s[e * CAPV + cc0]; }
    if (cc1 < cnt) { m1 = g_slot_m[e * CAPV + cc1]; s1 = g_slot_s[e * CAPV + cc1]; }
#pragma unroll
    for (int ni = 0; ni < 4; ni++) {
        int colg = bn + wn + ni * 8 + tg * 2;
        float2 bb = *(const float2*)&bp[colg];
        if (m0 >= 0)
            *(unsigned*)&g_ya[(size_t)m0 * HIDV + colg] =
                pkh2(s0 * (acc[ni][0] + bb.x), s0 * (acc[ni][1] + bb.y));
        if (m1 >= 0)
            *(unsigned*)&g_ya[(size_t)m1 * HIDV + colg] =
                pkh2(s1 * (acc[ni][2] + bb.x), s1 * (acc[ni][3] + bb.y));
    }
}

// ---------------- host ----------------
extern "C" void kernel_launch(void* const* d_in, const int* in_sizes, int n_in,
                              void* d_out, int out_size) {
    const float* x    = (const float*)d_in[0];
    const float* Wr   = (const float*)d_in[1];
    const float* br   = (const float*)d_in[2];
    const float* diag = (const float*)d_in[3];
    const float* Wp   = (const float*)d_in[4];
    const float* bp   = (const float*)d_in[5];
    const float* W1   = (const float*)d_in[6];
    const float* b1   = (const float*)d_in[7];
    const float* W2   = (const float*)d_in[8];
    const float* b2   = (const float*)d_in[9];
    float* out = (float*)d_out;

    float* p_logits = nullptr;
    void* p_xeff = nullptr;
    void* p_h = nullptr;
    cudaGetSymbolAddress((void**)&p_logits, g_logits);
    cudaGetSymbolAddress(&p_xeff, g_xeff);
    cudaGetSymbolAddress(&p_h, g_h);

    // router logits (exact fp32) + fused top-8-bit |logit| histogram
    router_kernel<<<dim3(NE / 64, N_TOK / 64), 256>>>(x, Wr, br, p_logits);

    // exact order statistic a[419430] of |logits|: second hist pass (prefix recomputed
    // per-block), candidate collect, then single-block resolve (also restores state)
    hist16_kernel<<<512, 256>>>();
    collect_kernel<<<512, 256>>>();
    final_pick_kernel<<<1, 256>>>();

    topk_xeff_kernel<<<N_TOK / 4, 128>>>(x, diag);
    pos_kernel<<<NE, 256>>>();

    // LoRA down: h = relu(x_gathered @ W1^T + b1) -> fp16 (2 x 128-row tiles)
    mma_gemm_kernel<1, DIMV><<<dim3(1, CAPV / 128, NE), 256>>>(x, W1, b1, nullptr, RNK);

    // LoRA up main: rows 0..127 per expert
    mma_gemm_kernel<2, RNK><<<dim3(HIDV / 128, 1, NE), 256>>>((const float*)p_h, W2, b2, nullptr, HIDV);

    // LoRA up overflow: rows 128..cnt in 32-row tiles (most blocks exit immediately)
    gemm2ov_kernel<<<dim3(HIDV / 128, 4, NE), 256>>>(W2, b2);

    // diag path + fused combine: out = xeff @ Wp^T + bp + sum_k ya[4n+k]
    mma_gemm_kernel<0, DIMV><<<dim3(HIDV / 128, N_TOK / 128), 256>>>((const float*)p_xeff, Wp, bp, out, HIDV);
}